// round 5
// baseline (speedup 1.0000x reference)
#include <cuda_runtime.h>
#include <math.h>

#define Bn 512
#define Tn 128
#define En 128
#define Hn 256
#define G4 1024
#define KTAGS 10

typedef unsigned long long ull;

// ---------------- scratch (static device globals; no allocation) ----------------
__device__ float g_hall[(size_t)Bn * Tn * 2 * Hn];   // [b][t][512] concat(fwd,bwd)
__device__ float g_hstate[2][2][Bn][Hn];             // [ping][dir][b][h]
__device__ float g_c[2][Bn][Hn];                     // [dir][b][h]
__device__ int   g_len[Bn];
__device__ float g_WU[2][384][G4];                   // permuted [dir][k (W:0-127, U:128-383)][n=cell*4+gate]
__device__ float g_bp[2][G4];                        // permuted bias

// ---------------- f32x2 packed helpers ----------------
__device__ __forceinline__ ull pk(float lo, float hi) {
    ull r; asm("mov.b64 %0, {%1, %2};" : "=l"(r) : "f"(lo), "f"(hi)); return r;
}
__device__ __forceinline__ void ffma2(ull& d, ull a, ull b) {
    asm("fma.rn.f32x2 %0, %1, %2, %0;" : "+l"(d) : "l"(a), "l"(b));
}
__device__ __forceinline__ float upk_lo(ull v) { return __uint_as_float((unsigned)(v & 0xffffffffULL)); }
__device__ __forceinline__ float upk_hi(ull v) { return __uint_as_float((unsigned)(v >> 32)); }
__device__ __forceinline__ float sigm(float x) { return 1.0f / (1.0f + expf(-x)); }

// ---------------- weight permutation + lengths (once per launch) ----------------
__global__ void __launch_bounds__(256)
prep_kernel(const int* __restrict__ word,
            const float* __restrict__ Wf, const float* __restrict__ Uf, const float* __restrict__ bf,
            const float* __restrict__ Wb, const float* __restrict__ Ub, const float* __restrict__ bb,
            float* __restrict__ out_len)
{
    int idx = blockIdx.x * 256 + threadIdx.x;
    int total = 2 * 384 * G4;
    if (idx < total) {
        int dir = idx / (384 * G4);
        int rem = idx % (384 * G4);
        int row = rem / G4;
        int n   = rem % G4;
        int col = (n & 3) * Hn + (n >> 2);
        float v;
        if (row < 128) v = (dir ? Wb : Wf)[row * G4 + col];
        else           v = (dir ? Ub : Uf)[(row - 128) * G4 + col];
        g_WU[dir][row][n] = v;
    }
    if (idx < 2 * G4) {
        int dir = idx >> 10, n = idx & 1023;
        int col = (n & 3) * Hn + (n >> 2);
        g_bp[dir][n] = (dir ? bb : bf)[col];
    }
    if (idx < Bn) {
        const int* w = word + (size_t)idx * Tn;
        int c = 0;
        #pragma unroll 8
        for (int t = 0; t < Tn; t++) c += (w[t] != 0);
        g_len[idx] = c;
        out_len[idx] = (float)c;
    }
}

// ---------------- fused LSTM step ----------------
// grid (8 batch tiles, 8 cell chunks of 32, 2 dirs) = 128 CTAs, 128 threads.
// Tile 64 rows x 128 gate cols; each thread 8 rows x 8 gate cols (2 cells).
struct StepSmem {
    ull   A[2][32][64];     // [buf][k][m] duplicated (a,a)
    float B[2][32][128];    // [buf][k][n] permuted gate columns
};

__global__ void __launch_bounds__(128, 1)
lstm_step(int s,
          const int* __restrict__ word,
          const float* __restrict__ emb)
{
    extern __shared__ char smem_raw[];
    StepSmem* S = (StepSmem*)smem_raw;

    const int dir = blockIdx.z;
    const int t   = dir ? (Tn - 1 - s) : s;
    const int b0  = blockIdx.x * 64;
    const int n_base = blockIdx.y * 128;    // gate-col base
    const int j0  = blockIdx.y * 32;        // cell base

    const int tid = threadIdx.x;            // 0..127
    const int tx = tid & 15;                // gate cols tx*8..+7  (cells j0+2tx, j0+2tx+1)
    const int ty = tid >> 4;                // rows ty*8..+7

    // loader roles
    const int am  = tid & 63;               // A row
    const int ak0 = (tid >> 6) * 16;        // A k offset (0 or 16)
    const int bk  = tid >> 2;               // B k row (0..31)
    const int bn0 = (tid & 3) * 32;         // B n offset

    const int ping = s & 1;
    const float* hprev = &g_hstate[ping][dir][0][0];
    const int nch = (s == 0) ? 4 : 12;

    // acc[r][p]: r row 0..7, p col-pair 0..3 (cols tx*8+2p, +2p+1)
    ull acc[8][4];
    {
        ulonglong2 q0 = *(const ulonglong2*)&g_bp[dir][n_base + tx * 8];
        ulonglong2 q1 = *(const ulonglong2*)&g_bp[dir][n_base + tx * 8 + 4];
        #pragma unroll
        for (int r = 0; r < 8; r++) {
            acc[r][0] = q0.x; acc[r][1] = q0.y;
            acc[r][2] = q1.x; acc[r][3] = q1.y;
        }
    }

    // A global sources
    const int wtok = __ldg(&word[(size_t)(b0 + am) * Tn + t]);
    const float* aph1 = emb + (size_t)wtok * En + ak0;
    const float* aph2 = hprev + (size_t)(b0 + am) * Hn + ak0;
    const float* bsrc0 = &g_WU[dir][bk][n_base + bn0];

    float4 ra[4], rb[8];
    auto rload = [&](int kc) {
        const int kb = kc * 32;
        const float* ap = (kb < 128) ? (aph1 + kb) : (aph2 + (kb - 128));
        #pragma unroll
        for (int i = 0; i < 4; i++) ra[i] = *(const float4*)(ap + 4 * i);
        const float* bp = bsrc0 + (size_t)kb * G4;
        #pragma unroll
        for (int i = 0; i < 8; i++) rb[i] = *(const float4*)(bp + 4 * i);
    };
    auto rstore = [&](int buf) {
        #pragma unroll
        for (int i = 0; i < 4; i++) {
            S->A[buf][ak0 + 4 * i + 0][am] = pk(ra[i].x, ra[i].x);
            S->A[buf][ak0 + 4 * i + 1][am] = pk(ra[i].y, ra[i].y);
            S->A[buf][ak0 + 4 * i + 2][am] = pk(ra[i].z, ra[i].z);
            S->A[buf][ak0 + 4 * i + 3][am] = pk(ra[i].w, ra[i].w);
        }
        #pragma unroll
        for (int i = 0; i < 8; i++)
            *(float4*)&S->B[buf][bk][bn0 + 4 * i] = rb[i];
    };

    rload(0); rstore(0);
    __syncthreads();

    for (int kc = 0; kc < nch; kc++) {
        const int buf = kc & 1;
        if (kc + 1 < nch) rload(kc + 1);

        #pragma unroll 8
        for (int kl = 0; kl < 32; kl++) {
            ulonglong2 a01 = *(const ulonglong2*)&S->A[buf][kl][ty * 8 + 0];
            ulonglong2 a23 = *(const ulonglong2*)&S->A[buf][kl][ty * 8 + 2];
            ulonglong2 a45 = *(const ulonglong2*)&S->A[buf][kl][ty * 8 + 4];
            ulonglong2 a67 = *(const ulonglong2*)&S->A[buf][kl][ty * 8 + 6];
            ulonglong2 bq0 = *(const ulonglong2*)&S->B[buf][kl][tx * 8];
            ulonglong2 bq1 = *(const ulonglong2*)&S->B[buf][kl][tx * 8 + 4];
            ull ar[8] = {a01.x, a01.y, a23.x, a23.y, a45.x, a45.y, a67.x, a67.y};
            ull bp[4] = {bq0.x, bq0.y, bq1.x, bq1.y};
            #pragma unroll
            for (int r = 0; r < 8; r++) {
                ffma2(acc[r][0], ar[r], bp[0]);
                ffma2(acc[r][1], ar[r], bp[1]);
                ffma2(acc[r][2], ar[r], bp[2]);
                ffma2(acc[r][3], ar[r], bp[3]);
            }
        }
        if (kc + 1 < nch) {
            rstore(buf ^ 1);
            __syncthreads();
        }
    }

    // ---- pointwise LSTM epilogue (8 rows x 2 cells per thread) ----
    const int pingW = ping ^ 1;
    #pragma unroll
    for (int r = 0; r < 8; r++) {
        const int b = b0 + ty * 8 + r;
        #pragma unroll
        for (int c = 0; c < 2; c++) {
            const int jj = j0 + 2 * tx + c;
            float iv = upk_lo(acc[r][2 * c + 0]), fv = upk_hi(acc[r][2 * c + 0]);
            float gv = upk_lo(acc[r][2 * c + 1]), ov = upk_hi(acc[r][2 * c + 1]);
            float cp = (s == 0) ? 0.0f : g_c[dir][b][jj];
            float ii = sigm(iv);
            float ff = sigm(fv);
            float gg = tanhf(gv);
            float oo = sigm(ov);
            float cn = ff * cp + ii * gg;
            float hn = oo * tanhf(cn);
            g_c[dir][b][jj] = cn;
            g_hstate[pingW][dir][b][jj] = hn;
            g_hall[((size_t)b * Tn + t) * (2 * Hn) + dir * Hn + jj] = hn;
        }
    }
}

// ---------------- dense + softmax ----------------
__global__ void __launch_bounds__(256)
dense_softmax(const float* __restrict__ Wd, const float* __restrict__ bd, float* __restrict__ probs)
{
    __shared__ float wd_s[KTAGS][2 * Hn];
    __shared__ float bd_s[KTAGS];
    const int tid = threadIdx.x;
    for (int i = tid; i < 2 * Hn * KTAGS; i += 256) {
        int e = i / KTAGS, k = i % KTAGS;
        wd_s[k][e] = Wd[i];
    }
    if (tid < KTAGS) bd_s[tid] = bd[tid];
    __syncthreads();

    const int warp = tid >> 5, lane = tid & 31;
    const size_t row = (size_t)blockIdx.x * 8 + warp;
    const float* h = &g_hall[row * (2 * Hn)];

    float acc[KTAGS];
    #pragma unroll
    for (int k = 0; k < KTAGS; k++) acc[k] = 0.0f;

    #pragma unroll
    for (int q = 0; q < 16; q++) {
        int e = lane + 32 * q;
        float hv = h[e];
        #pragma unroll
        for (int k = 0; k < KTAGS; k++) acc[k] += hv * wd_s[k][e];
    }
    #pragma unroll
    for (int k = 0; k < KTAGS; k++) {
        #pragma unroll
        for (int off = 16; off > 0; off >>= 1)
            acc[k] += __shfl_xor_sync(0xffffffffu, acc[k], off);
        acc[k] += bd_s[k];
    }
    float mx = acc[0];
    #pragma unroll
    for (int k = 1; k < KTAGS; k++) mx = fmaxf(mx, acc[k]);
    float den = 0.0f;
    #pragma unroll
    for (int k = 0; k < KTAGS; k++) den += expf(acc[k] - mx);
    float inv = 1.0f / den;
    #pragma unroll
    for (int k = 0; k < KTAGS; k++) {
        float pv = expf(acc[k] - mx) * inv;
        if (lane == k) probs[row * KTAGS + k] = pv;
    }
}

// ---------------- CRF log-likelihood ----------------
__global__ void crf_kernel(const int* __restrict__ label,
                           const float* __restrict__ trans,
                           const float* __restrict__ probs,
                           float* __restrict__ out_ll)
{
    const int b = blockIdx.x;
    const int lane = threadIdx.x;
    const int len = g_len[b];
    const float* P = probs + (size_t)b * Tn * KTAGS;
    const int* tg = label + (size_t)b * Tn;

    float u = 0.0f;
    for (int t = lane; t < Tn; t += 32)
        if (t < len) u += P[t * KTAGS + tg[t]];
    float bi = 0.0f;
    for (int t = lane; t < Tn - 1; t += 32)
        if (t < len - 1) bi += trans[tg[t] * KTAGS + tg[t + 1]];
    #pragma unroll
    for (int off = 16; off > 0; off >>= 1) {
        u  += __shfl_xor_sync(0xffffffffu, u, off);
        bi += __shfl_xor_sync(0xffffffffu, bi, off);
    }

    const int kk = (lane < KTAGS) ? lane : 0;
    float tr[KTAGS];
    #pragma unroll
    for (int j = 0; j < KTAGS; j++) tr[j] = trans[j * KTAGS + kk];

    float alpha = (lane < KTAGS) ? P[kk] : -1e30f;
    for (int t = 1; t < Tn; t++) {
        float aj[KTAGS];
        #pragma unroll
        for (int j = 0; j < KTAGS; j++) aj[j] = __shfl_sync(0xffffffffu, alpha, j);
        float m = -1e30f;
        #pragma unroll
        for (int j = 0; j < KTAGS; j++) m = fmaxf(m, aj[j] + tr[j]);
        float sum = 0.0f;
        #pragma unroll
        for (int j = 0; j < KTAGS; j++) sum += expf(aj[j] + tr[j] - m);
        float nv = m + logf(sum) + P[t * KTAGS + kk];
        if (t < len && lane < KTAGS) alpha = nv;
    }
    float aj[KTAGS];
    #pragma unroll
    for (int j = 0; j < KTAGS; j++) aj[j] = __shfl_sync(0xffffffffu, alpha, j);
    float m = -1e30f;
    #pragma unroll
    for (int j = 0; j < KTAGS; j++) m = fmaxf(m, aj[j]);
    float sum = 0.0f;
    #pragma unroll
    for (int j = 0; j < KTAGS; j++) sum += expf(aj[j] - m);
    float ln = (len == 0) ? 0.0f : (m + logf(sum));

    if (lane == 0) out_ll[b] = u + bi - ln;
}

// ---------------- launch ----------------
extern "C" void kernel_launch(void* const* d_in, const int* in_sizes, int n_in,
                              void* d_out, int out_size)
{
    const int*   word  = (const int*)d_in[0];
    const int*   label = (const int*)d_in[1];
    const float* emb   = (const float*)d_in[2];
    const float* Wf    = (const float*)d_in[3];
    const float* Uf    = (const float*)d_in[4];
    const float* bf    = (const float*)d_in[5];
    const float* Wb    = (const float*)d_in[6];
    const float* Ub    = (const float*)d_in[7];
    const float* bb    = (const float*)d_in[8];
    const float* Wd    = (const float*)d_in[9];
    const float* bd    = (const float*)d_in[10];
    const float* trans = (const float*)d_in[11];

    float* out      = (float*)d_out;
    float* probs    = out;                                 // 512*128*10
    float* out_len  = out + (size_t)Bn * Tn * KTAGS;       // 512
    float* out_ll   = out_len + Bn;                        // 512

    const int smem_bytes = (int)sizeof(StepSmem);
    cudaFuncSetAttribute(lstm_step, cudaFuncAttributeMaxDynamicSharedMemorySize, smem_bytes);

    prep_kernel<<<(2 * 384 * G4 + 255) / 256, 256>>>(word, Wf, Uf, bf, Wb, Ub, bb, out_len);

    dim3 grid(8, 8, 2);
    for (int s = 0; s < Tn; s++)
        lstm_step<<<grid, 128, smem_bytes>>>(s, word, emb);

    dense_softmax<<<8192, 256>>>(Wd, bd, probs);
    crf_kernel<<<Bn, 32>>>(label, trans, probs, out_ll);
}

// round 7
// speedup vs baseline: 2.2680x; 2.2680x over previous
#include <cuda_runtime.h>
#include <cuda_bf16.h>
#include <math.h>
#include <stdint.h>

#define Bn 512
#define Tn 128
#define En 128
#define Hn 256
#define G4 1024
#define KTAGS 10
#define VOCABN 30001

// ---------------- scratch (static device globals; no allocation) ----------------
__device__ float g_hall[(size_t)Bn * Tn * 2 * Hn];          // [b][t][512]
__device__ float g_c2[2 * Bn * Hn];                         // [dir][b][h]
__device__ int   g_len[Bn];
__device__ float g_bp[2 * G4];                              // permuted bias (fp32)
__device__ float g_xw[(size_t)2 * Tn * Bn * G4];            // [dir][t][b][np]  (536MB, bias folded)
__device__ __nv_bfloat16 g_ehi[(size_t)VOCABN * En];
__device__ __nv_bfloat16 g_elo[(size_t)VOCABN * En];
__device__ __nv_bfloat16 g_hhi[2 * 2 * Bn * Hn];            // [ping][dir][b][h]
__device__ __nv_bfloat16 g_hlo[2 * 2 * Bn * Hn];
__device__ __nv_bfloat16 g_Wp[2 * 2 * En * G4];             // [dir][split][k<128][np]
__device__ __nv_bfloat16 g_Up[2 * 2 * Hn * G4];             // [dir][split][k<256][np]

__device__ __forceinline__ float sigm(float x) { return 1.0f / (1.0f + expf(-x)); }

__device__ __forceinline__ uint32_t smem_u32(const void* p) {
    uint32_t a;
    asm("{ .reg .u64 t; cvta.to.shared.u64 t, %1; cvt.u32.u64 %0, t; }" : "=r"(a) : "l"(p));
    return a;
}
__device__ __forceinline__ void ldsm4(uint32_t& r0, uint32_t& r1, uint32_t& r2, uint32_t& r3, uint32_t addr) {
    asm volatile("ldmatrix.sync.aligned.m8n8.x4.shared.b16 {%0,%1,%2,%3}, [%4];"
                 : "=r"(r0), "=r"(r1), "=r"(r2), "=r"(r3) : "r"(addr));
}
__device__ __forceinline__ void ldsm4t(uint32_t& r0, uint32_t& r1, uint32_t& r2, uint32_t& r3, uint32_t addr) {
    asm volatile("ldmatrix.sync.aligned.m8n8.x4.trans.shared.b16 {%0,%1,%2,%3}, [%4];"
                 : "=r"(r0), "=r"(r1), "=r"(r2), "=r"(r3) : "r"(addr));
}
__device__ __forceinline__ void mma16816(float* d, const uint32_t* a, uint32_t b0, uint32_t b1) {
    asm volatile("mma.sync.aligned.m16n8k16.row.col.f32.bf16.bf16.f32 "
                 "{%0,%1,%2,%3}, {%4,%5,%6,%7}, {%8,%9}, {%0,%1,%2,%3};"
                 : "+f"(d[0]), "+f"(d[1]), "+f"(d[2]), "+f"(d[3])
                 : "r"(a[0]), "r"(a[1]), "r"(a[2]), "r"(a[3]), "r"(b0), "r"(b1));
}

// ---------------- prep: splits, permuted weights/bias, zero h, lengths ----------------
__global__ void __launch_bounds__(256)
prep_kernel(const int* __restrict__ word,
            const float* __restrict__ emb,
            const float* __restrict__ Wf, const float* __restrict__ Uf, const float* __restrict__ bf,
            const float* __restrict__ Wb, const float* __restrict__ Ub, const float* __restrict__ bb,
            float* __restrict__ out_len)
{
    size_t idx = (size_t)blockIdx.x * 256 + threadIdx.x;

    if (idx < (size_t)VOCABN * En) {
        float v = emb[idx];
        __nv_bfloat16 hi = __float2bfloat16_rn(v);
        g_ehi[idx] = hi;
        g_elo[idx] = __float2bfloat16_rn(v - __bfloat162float(hi));
    }
    if (idx < (size_t)2 * 384 * G4) {
        int dir = (int)(idx / (384 * G4));
        int rem = (int)(idx % (384 * G4));
        int k   = rem / G4;
        int np  = rem % G4;
        int col = (np & 3) * Hn + (np >> 2);
        float v;
        if (k < En) v = (dir ? Wb : Wf)[k * G4 + col];
        else        v = (dir ? Ub : Uf)[(k - En) * G4 + col];
        __nv_bfloat16 hi = __float2bfloat16_rn(v);
        __nv_bfloat16 lo = __float2bfloat16_rn(v - __bfloat162float(hi));
        if (k < En) {
            g_Wp[((size_t)dir * 2 + 0) * En * G4 + (size_t)k * G4 + np] = hi;
            g_Wp[((size_t)dir * 2 + 1) * En * G4 + (size_t)k * G4 + np] = lo;
        } else {
            g_Up[((size_t)dir * 2 + 0) * Hn * G4 + (size_t)(k - En) * G4 + np] = hi;
            g_Up[((size_t)dir * 2 + 1) * Hn * G4 + (size_t)(k - En) * G4 + np] = lo;
        }
    }
    if (idx < (size_t)2 * 2 * Bn * Hn) {
        g_hhi[idx] = __float2bfloat16_rn(0.0f);
        g_hlo[idx] = __float2bfloat16_rn(0.0f);
    }
    if (idx < 2 * G4) {
        int dir = (int)(idx >> 10), np = (int)(idx & 1023);
        int col = (np & 3) * Hn + (np >> 2);
        g_bp[idx] = (dir ? bb : bf)[col];
    }
    if (idx < Bn) {
        const int* w = word + idx * Tn;
        int c = 0;
        #pragma unroll 8
        for (int t = 0; t < Tn; t++) c += (w[t] != 0);
        g_len[idx] = c;
        out_len[idx] = (float)c;
    }
}

// ---------------- shared GEMM smem layout (55296 B, dynamic) ----------------
// A hi: [buf][64][40] bf16 ; A lo ; B hi: [buf][32][136] bf16 ; B lo
#define R_AHI(buf) ((buf) * 5120)
#define R_ALO(buf) (10240 + (buf) * 5120)
#define R_BHI(buf) (20480 + (buf) * 8704)
#define R_BLO(buf) (37888 + (buf) * 8704)
#define SM_SIZE 55296

// compute one k32 chunk from smem buffers into acc[8][4]
__device__ __forceinline__ void gemm_chunk(char* sm, uint32_t smb, int buf,
                                           int wm, int wn, int lane, float acc[8][4])
{
    #pragma unroll
    for (int k16 = 0; k16 < 2; k16++) {
        uint32_t ah[4], al[4];
        {
            int mrow = wm * 16 + ((lane >> 3) & 1) * 8 + (lane & 7);
            int kcol = k16 * 16 + (lane >> 4) * 8;
            uint32_t off = (uint32_t)(mrow * 40 + kcol) * 2;
            ldsm4(ah[0], ah[1], ah[2], ah[3], smb + R_AHI(buf) + off);
            ldsm4(al[0], al[1], al[2], al[3], smb + R_ALO(buf) + off);
        }
        uint32_t bh[16], bl[16];
        {
            int krow = k16 * 16 + ((lane >> 3) & 1) * 8 + (lane & 7);
            #pragma unroll
            for (int nb = 0; nb < 4; nb++) {
                int ncol = wn * 64 + nb * 16 + (lane >> 4) * 8;
                uint32_t off = (uint32_t)(krow * 136 + ncol) * 2;
                ldsm4t(bh[nb * 4 + 0], bh[nb * 4 + 1], bh[nb * 4 + 2], bh[nb * 4 + 3], smb + R_BHI(buf) + off);
                ldsm4t(bl[nb * 4 + 0], bl[nb * 4 + 1], bl[nb * 4 + 2], bl[nb * 4 + 3], smb + R_BLO(buf) + off);
            }
        }
        #pragma unroll
        for (int nf = 0; nf < 8; nf++) {
            mma16816(acc[nf], ah, bh[nf * 2], bh[nf * 2 + 1]);
            mma16816(acc[nf], ah, bl[nf * 2], bl[nf * 2 + 1]);
            mma16816(acc[nf], al, bh[nf * 2], bh[nf * 2 + 1]);
        }
    }
}

// ---------------- XW precompute: xw[dir][t][b][np] = emb[word]@W + bias ----------------
// grid (8 btiles, 8 ntiles, 256 = t*2+dir), 256 threads.
__global__ void __launch_bounds__(256)
xw_kernel(const int* __restrict__ word)
{
    extern __shared__ char sm[];
    const uint32_t smb = smem_u32(sm);

    const int dir = blockIdx.z & 1;
    const int t   = blockIdx.z >> 1;
    const int b0  = blockIdx.x * 64;
    const int ntile = blockIdx.y;
    const int tid = threadIdx.x;
    const int wid = tid >> 5, lane = tid & 31;
    const int wm = wid & 3, wn = wid >> 2;

    // acc init: bias
    float acc[8][4];
    const int colb = ntile * 128 + wn * 64 + (lane & 3) * 2;
    #pragma unroll
    for (int nf = 0; nf < 8; nf++) {
        float2 bb0 = *(const float2*)&g_bp[dir * G4 + colb + nf * 8];
        acc[nf][0] = bb0.x; acc[nf][1] = bb0.y; acc[nf][2] = bb0.x; acc[nf][3] = bb0.y;
    }

    const __nv_bfloat16* whi = g_Wp + ((size_t)dir * 2 + 0) * En * G4 + ntile * 128;
    const __nv_bfloat16* wlo = g_Wp + ((size_t)dir * 2 + 1) * En * G4 + ntile * 128;

    const int am = tid >> 2, akk = (tid & 3) * 8;
    const int bk = tid >> 3, bn0 = (tid & 7) * 16;
    const int tok = word[(size_t)(b0 + am) * Tn + t];
    const __nv_bfloat16* ehi = g_ehi + (size_t)tok * En + akk;
    const __nv_bfloat16* elo = g_elo + (size_t)tok * En + akk;

    uint4 rah, ral, rbh0, rbh1, rbl0, rbl1;
    auto rload = [&](int c) {
        int kb = c * 32;
        rah = *(const uint4*)(ehi + kb);
        ral = *(const uint4*)(elo + kb);
        const __nv_bfloat16* p = whi + (size_t)(kb + bk) * G4 + bn0;
        rbh0 = *(const uint4*)p; rbh1 = *(const uint4*)(p + 8);
        p = wlo + (size_t)(kb + bk) * G4 + bn0;
        rbl0 = *(const uint4*)p; rbl1 = *(const uint4*)(p + 8);
    };
    auto rstore = [&](int buf) {
        *(uint4*)(sm + R_AHI(buf) + (am * 40 + akk) * 2) = rah;
        *(uint4*)(sm + R_ALO(buf) + (am * 40 + akk) * 2) = ral;
        *(uint4*)(sm + R_BHI(buf) + (bk * 136 + bn0) * 2) = rbh0;
        *(uint4*)(sm + R_BHI(buf) + (bk * 136 + bn0) * 2 + 16) = rbh1;
        *(uint4*)(sm + R_BLO(buf) + (bk * 136 + bn0) * 2) = rbl0;
        *(uint4*)(sm + R_BLO(buf) + (bk * 136 + bn0) * 2 + 16) = rbl1;
    };

    rload(0); rstore(0);
    __syncthreads();
    for (int c = 0; c < 4; c++) {
        int buf = c & 1;
        if (c < 3) rload(c + 1);
        gemm_chunk(sm, smb, buf, wm, wn, lane, acc);
        __syncthreads();
        if (c < 3) { rstore(buf ^ 1); __syncthreads(); }
    }

    // store fragments
    float* xwp = g_xw + ((size_t)dir * Tn + t) * Bn * G4;
    const int m0 = b0 + wm * 16 + (lane >> 2);
    #pragma unroll
    for (int nf = 0; nf < 8; nf++) {
        *(float2*)&xwp[(size_t)m0 * G4 + colb + nf * 8]       = make_float2(acc[nf][0], acc[nf][1]);
        *(float2*)&xwp[(size_t)(m0 + 8) * G4 + colb + nf * 8] = make_float2(acc[nf][2], acc[nf][3]);
    }
}

// ---------------- recurrent step: z = xw_t + h@U, gates ----------------
// grid (8 btiles, 8 ntiles, 2 dirs) = 128 CTAs, 256 threads.
__global__ void __launch_bounds__(256)
lstm_step(int s, const int* __restrict__ word)
{
    extern __shared__ char sm[];
    const uint32_t smb = smem_u32(sm);

    const int dir = blockIdx.z;
    const int t   = dir ? (Tn - 1 - s) : s;
    const int b0  = blockIdx.x * 64;
    const int ntile = blockIdx.y;
    const int tid = threadIdx.x;
    const int wid = tid >> 5, lane = tid & 31;
    const int wm = wid & 3, wn = wid >> 2;
    const int ping = s & 1;

    // acc init from precomputed xw (bias already folded)
    float acc[8][4];
    const float* xwp = g_xw + ((size_t)dir * Tn + t) * Bn * G4;
    const int colb = ntile * 128 + wn * 64 + (lane & 3) * 2;
    const int m0 = b0 + wm * 16 + (lane >> 2);
    #pragma unroll
    for (int nf = 0; nf < 8; nf++) {
        float2 v0 = *(const float2*)&xwp[(size_t)m0 * G4 + colb + nf * 8];
        float2 v1 = *(const float2*)&xwp[(size_t)(m0 + 8) * G4 + colb + nf * 8];
        acc[nf][0] = v0.x; acc[nf][1] = v0.y; acc[nf][2] = v1.x; acc[nf][3] = v1.y;
    }

    if (s > 0) {
        const __nv_bfloat16* hhi = g_hhi + (size_t)(ping * 2 + dir) * Bn * Hn;
        const __nv_bfloat16* hlo = g_hlo + (size_t)(ping * 2 + dir) * Bn * Hn;
        const __nv_bfloat16* uhi = g_Up + ((size_t)dir * 2 + 0) * Hn * G4 + ntile * 128;
        const __nv_bfloat16* ulo = g_Up + ((size_t)dir * 2 + 1) * Hn * G4 + ntile * 128;

        const int am = tid >> 2, akk = (tid & 3) * 8;
        const int bk = tid >> 3, bn0 = (tid & 7) * 16;
        const __nv_bfloat16* ahsrc = hhi + (size_t)(b0 + am) * Hn + akk;
        const __nv_bfloat16* alsrc = hlo + (size_t)(b0 + am) * Hn + akk;

        uint4 rah, ral, rbh0, rbh1, rbl0, rbl1;
        auto rload = [&](int c) {
            int kb = c * 32;
            rah = *(const uint4*)(ahsrc + kb);
            ral = *(const uint4*)(alsrc + kb);
            const __nv_bfloat16* p = uhi + (size_t)(kb + bk) * G4 + bn0;
            rbh0 = *(const uint4*)p; rbh1 = *(const uint4*)(p + 8);
            p = ulo + (size_t)(kb + bk) * G4 + bn0;
            rbl0 = *(const uint4*)p; rbl1 = *(const uint4*)(p + 8);
        };
        auto rstore = [&](int buf) {
            *(uint4*)(sm + R_AHI(buf) + (am * 40 + akk) * 2) = rah;
            *(uint4*)(sm + R_ALO(buf) + (am * 40 + akk) * 2) = ral;
            *(uint4*)(sm + R_BHI(buf) + (bk * 136 + bn0) * 2) = rbh0;
            *(uint4*)(sm + R_BHI(buf) + (bk * 136 + bn0) * 2 + 16) = rbh1;
            *(uint4*)(sm + R_BLO(buf) + (bk * 136 + bn0) * 2) = rbl0;
            *(uint4*)(sm + R_BLO(buf) + (bk * 136 + bn0) * 2 + 16) = rbl1;
        };

        rload(0); rstore(0);
        __syncthreads();
        for (int c = 0; c < 8; c++) {
            int buf = c & 1;
            if (c < 7) rload(c + 1);
            gemm_chunk(sm, smb, buf, wm, wn, lane, acc);
            __syncthreads();
            if (c < 7) { rstore(buf ^ 1); __syncthreads(); }
        }
    } else {
        __syncthreads();
    }

    // ---- epilogue via SMEM round-trip (reuses GEMM buffers) ----
    float* Cs = (float*)sm;          // [64][132]
    const int r0 = wm * 16 + (lane >> 2);
    const int cl = wn * 64 + (lane & 3) * 2;
    #pragma unroll
    for (int nf = 0; nf < 8; nf++) {
        *(float2*)&Cs[r0 * 132 + cl + nf * 8]       = make_float2(acc[nf][0], acc[nf][1]);
        *(float2*)&Cs[(r0 + 8) * 132 + cl + nf * 8] = make_float2(acc[nf][2], acc[nf][3]);
    }
    __syncthreads();

    const int row = tid >> 2;            // 0..63
    const int cb  = tid & 3;             // cell block: 8 cells
    const int b   = b0 + row;
    const int pingW = ping ^ 1;
    __nv_bfloat16* whhi = g_hhi + (size_t)(pingW * 2 + dir) * Bn * Hn;
    __nv_bfloat16* whlo = g_hlo + (size_t)(pingW * 2 + dir) * Bn * Hn;
    float* crow = g_c2 + ((size_t)dir * Bn + b) * Hn;
    float* hall = g_hall + ((size_t)b * Tn + t) * (2 * Hn) + dir * Hn;

    #pragma unroll
    for (int q = 0; q < 8; q++) {
        const int jl = cb * 8 + q;               // local cell 0..31
        const int j  = ntile * 32 + jl;
        float iv = Cs[row * 132 + jl * 4 + 0];
        float fv = Cs[row * 132 + jl * 4 + 1];
        float gv = Cs[row * 132 + jl * 4 + 2];
        float ov = Cs[row * 132 + jl * 4 + 3];
        float cp = (s == 0) ? 0.0f : crow[j];
        float ii = sigm(iv);
        float ff = sigm(fv);
        float gg = tanhf(gv);
        float oo = sigm(ov);
        float cn = ff * cp + ii * gg;
        float hn = oo * tanhf(cn);
        crow[j] = cn;
        hall[j] = hn;
        __nv_bfloat16 hi = __float2bfloat16_rn(hn);
        whhi[(size_t)b * Hn + j] = hi;
        whlo[(size_t)b * Hn + j] = __float2bfloat16_rn(hn - __bfloat162float(hi));
    }
}

// ---------------- dense + softmax ----------------
__global__ void __launch_bounds__(256)
dense_softmax(const float* __restrict__ Wd, const float* __restrict__ bd, float* __restrict__ probs)
{
    __shared__ float wd_s[KTAGS][2 * Hn];
    __shared__ float bd_s[KTAGS];
    const int tid = threadIdx.x;
    for (int i = tid; i < 2 * Hn * KTAGS; i += 256) {
        int e = i / KTAGS, k = i % KTAGS;
        wd_s[k][e] = Wd[i];
    }
    if (tid < KTAGS) bd_s[tid] = bd[tid];
    __syncthreads();

    const int warp = tid >> 5, lane = tid & 31;
    const size_t row = (size_t)blockIdx.x * 8 + warp;
    const float* h = &g_hall[row * (2 * Hn)];

    float acc[KTAGS];
    #pragma unroll
    for (int k = 0; k < KTAGS; k++) acc[k] = 0.0f;
    #pragma unroll
    for (int q = 0; q < 16; q++) {
        int e = lane + 32 * q;
        float hv = h[e];
        #pragma unroll
        for (int k = 0; k < KTAGS; k++) acc[k] += hv * wd_s[k][e];
    }
    #pragma unroll
    for (int k = 0; k < KTAGS; k++) {
        #pragma unroll
        for (int off = 16; off > 0; off >>= 1)
            acc[k] += __shfl_xor_sync(0xffffffffu, acc[k], off);
        acc[k] += bd_s[k];
    }
    float mx = acc[0];
    #pragma unroll
    for (int k = 1; k < KTAGS; k++) mx = fmaxf(mx, acc[k]);
    float den = 0.0f;
    #pragma unroll
    for (int k = 0; k < KTAGS; k++) den += expf(acc[k] - mx);
    float inv = 1.0f / den;
    #pragma unroll
    for (int k = 0; k < KTAGS; k++) {
        float pv = expf(acc[k] - mx) * inv;
        if (lane == k) probs[row * KTAGS + k] = pv;
    }
}

// ---------------- CRF log-likelihood ----------------
__global__ void crf_kernel(const int* __restrict__ label,
                           const float* __restrict__ trans,
                           const float* __restrict__ probs,
                           float* __restrict__ out_ll)
{
    const int b = blockIdx.x;
    const int lane = threadIdx.x;
    const int len = g_len[b];
    const float* P = probs + (size_t)b * Tn * KTAGS;
    const int* tg = label + (size_t)b * Tn;

    float u = 0.0f;
    for (int t = lane; t < Tn; t += 32)
        if (t < len) u += P[t * KTAGS + tg[t]];
    float bi = 0.0f;
    for (int t = lane; t < Tn - 1; t += 32)
        if (t < len - 1) bi += trans[tg[t] * KTAGS + tg[t + 1]];
    #pragma unroll
    for (int off = 16; off > 0; off >>= 1) {
        u  += __shfl_xor_sync(0xffffffffu, u, off);
        bi += __shfl_xor_sync(0xffffffffu, bi, off);
    }

    const int kk = (lane < KTAGS) ? lane : 0;
    float tr[KTAGS];
    #pragma unroll
    for (int j = 0; j < KTAGS; j++) tr[j] = trans[j * KTAGS + kk];

    float alpha = (lane < KTAGS) ? P[kk] : -1e30f;
    for (int t = 1; t < Tn; t++) {
        float aj[KTAGS];
        #pragma unroll
        for (int j = 0; j < KTAGS; j++) aj[j] = __shfl_sync(0xffffffffu, alpha, j);
        float m = -1e30f;
        #pragma unroll
        for (int j = 0; j < KTAGS; j++) m = fmaxf(m, aj[j] + tr[j]);
        float sum = 0.0f;
        #pragma unroll
        for (int j = 0; j < KTAGS; j++) sum += expf(aj[j] + tr[j] - m);
        float nv = m + logf(sum) + P[t * KTAGS + kk];
        if (t < len && lane < KTAGS) alpha = nv;
    }
    float aj[KTAGS];
    #pragma unroll
    for (int j = 0; j < KTAGS; j++) aj[j] = __shfl_sync(0xffffffffu, alpha, j);
    float m = -1e30f;
    #pragma unroll
    for (int j = 0; j < KTAGS; j++) m = fmaxf(m, aj[j]);
    float sum = 0.0f;
    #pragma unroll
    for (int j = 0; j < KTAGS; j++) sum += expf(aj[j] - m);
    float ln = (len == 0) ? 0.0f : (m + logf(sum));

    if (lane == 0) out_ll[b] = u + bi - ln;
}

// ---------------- launch ----------------
extern "C" void kernel_launch(void* const* d_in, const int* in_sizes, int n_in,
                              void* d_out, int out_size)
{
    const int*   word  = (const int*)d_in[0];
    const int*   label = (const int*)d_in[1];
    const float* emb   = (const float*)d_in[2];
    const float* Wf    = (const float*)d_in[3];
    const float* Uf    = (const float*)d_in[4];
    const float* bf    = (const float*)d_in[5];
    const float* Wb    = (const float*)d_in[6];
    const float* Ub    = (const float*)d_in[7];
    const float* bb    = (const float*)d_in[8];
    const float* Wd    = (const float*)d_in[9];
    const float* bd    = (const float*)d_in[10];
    const float* trans = (const float*)d_in[11];

    float* out      = (float*)d_out;
    float* probs    = out;                                 // 512*128*10
    float* out_len  = out + (size_t)Bn * Tn * KTAGS;       // 512
    float* out_ll   = out_len + Bn;                        // 512

    cudaFuncSetAttribute(xw_kernel, cudaFuncAttributeMaxDynamicSharedMemorySize, SM_SIZE);
    cudaFuncSetAttribute(lstm_step, cudaFuncAttributeMaxDynamicSharedMemorySize, SM_SIZE);

    const size_t prep_n = (size_t)VOCABN * En;
    prep_kernel<<<(int)((prep_n + 255) / 256), 256>>>(word, emb, Wf, Uf, bf, Wb, Ub, bb, out_len);

    dim3 xwgrid(8, 8, 256);
    xw_kernel<<<xwgrid, 256, SM_SIZE>>>(word);

    dim3 grid(8, 8, 2);
    for (int s = 0; s < Tn; s++)
        lstm_step<<<grid, 256, SM_SIZE>>>(s, word);

    dense_softmax<<<8192, 256>>>(Wd, bd, probs);
    crf_kernel<<<Bn, 32>>>(label, trans, probs, out_ll);
}

// round 8
// speedup vs baseline: 2.8551x; 1.2589x over previous
#include <cuda_runtime.h>
#include <cuda_bf16.h>
#include <math.h>
#include <stdint.h>

#define Bn 512
#define Tn 128
#define En 128
#define Hn 256
#define G4 1024
#define KTAGS 10
#define VOCABN 30001

// ---------------- scratch (static device globals; no allocation) ----------------
__device__ float g_hall[(size_t)Bn * Tn * 2 * Hn];          // [b][t][512]
__device__ int   g_len[Bn];
__device__ float g_bp[2 * G4];                              // permuted bias (fp32)
__device__ float g_xw[(size_t)2 * Tn * Bn * G4];            // [dir][t][b][np] (bias folded)
__device__ __nv_bfloat16 g_ehi[(size_t)VOCABN * En];
__device__ __nv_bfloat16 g_elo[(size_t)VOCABN * En];
__device__ __nv_bfloat16 g_hhi[2 * 2 * Bn * Hn];            // [ping][dir][b][h]
__device__ __nv_bfloat16 g_hlo[2 * 2 * Bn * Hn];
__device__ __nv_bfloat16 g_Wp[2 * 2 * En * G4];             // [dir][split][k][np]
__device__ __nv_bfloat16 g_Up[2 * 2 * Hn * G4];             // [dir][split][k][np]
__device__ unsigned g_cnt[2][8][Tn];                        // step barriers (zeroed by prep)

__device__ __forceinline__ float sigm(float x) { return 1.0f / (1.0f + expf(-x)); }

__device__ __forceinline__ uint32_t smem_u32(const void* p) {
    uint32_t a;
    asm("{ .reg .u64 t; cvta.to.shared.u64 t, %1; cvt.u32.u64 %0, t; }" : "=r"(a) : "l"(p));
    return a;
}
__device__ __forceinline__ void ldsm4(uint32_t& r0, uint32_t& r1, uint32_t& r2, uint32_t& r3, uint32_t addr) {
    asm volatile("ldmatrix.sync.aligned.m8n8.x4.shared.b16 {%0,%1,%2,%3}, [%4];"
                 : "=r"(r0), "=r"(r1), "=r"(r2), "=r"(r3) : "r"(addr));
}
__device__ __forceinline__ void ldsm4t(uint32_t& r0, uint32_t& r1, uint32_t& r2, uint32_t& r3, uint32_t addr) {
    asm volatile("ldmatrix.sync.aligned.m8n8.x4.trans.shared.b16 {%0,%1,%2,%3}, [%4];"
                 : "=r"(r0), "=r"(r1), "=r"(r2), "=r"(r3) : "r"(addr));
}
__device__ __forceinline__ void mma16816(float* d, const uint32_t* a, uint32_t b0, uint32_t b1) {
    asm volatile("mma.sync.aligned.m16n8k16.row.col.f32.bf16.bf16.f32 "
                 "{%0,%1,%2,%3}, {%4,%5,%6,%7}, {%8,%9}, {%0,%1,%2,%3};"
                 : "+f"(d[0]), "+f"(d[1]), "+f"(d[2]), "+f"(d[3])
                 : "r"(a[0]), "r"(a[1]), "r"(a[2]), "r"(a[3]), "r"(b0), "r"(b1));
}
__device__ __forceinline__ unsigned ld_acq(const unsigned* p) {
    unsigned v;
    asm volatile("ld.global.acquire.gpu.u32 %0, [%1];" : "=r"(v) : "l"(p) : "memory");
    return v;
}

// ---------------- prep ----------------
__global__ void __launch_bounds__(256)
prep_kernel(const int* __restrict__ word,
            const float* __restrict__ emb,
            const float* __restrict__ Wf, const float* __restrict__ Uf, const float* __restrict__ bf,
            const float* __restrict__ Wb, const float* __restrict__ Ub, const float* __restrict__ bb,
            float* __restrict__ out_len)
{
    size_t idx = (size_t)blockIdx.x * 256 + threadIdx.x;

    if (idx < (size_t)VOCABN * En) {
        float v = emb[idx];
        __nv_bfloat16 hi = __float2bfloat16_rn(v);
        g_ehi[idx] = hi;
        g_elo[idx] = __float2bfloat16_rn(v - __bfloat162float(hi));
    }
    if (idx < (size_t)2 * 384 * G4) {
        int dir = (int)(idx / (384 * G4));
        int rem = (int)(idx % (384 * G4));
        int k   = rem / G4;
        int np  = rem % G4;
        int col = (np & 3) * Hn + (np >> 2);
        float v;
        if (k < En) v = (dir ? Wb : Wf)[k * G4 + col];
        else        v = (dir ? Ub : Uf)[(k - En) * G4 + col];
        __nv_bfloat16 hi = __float2bfloat16_rn(v);
        __nv_bfloat16 lo = __float2bfloat16_rn(v - __bfloat162float(hi));
        if (k < En) {
            g_Wp[((size_t)dir * 2 + 0) * En * G4 + (size_t)k * G4 + np] = hi;
            g_Wp[((size_t)dir * 2 + 1) * En * G4 + (size_t)k * G4 + np] = lo;
        } else {
            g_Up[((size_t)dir * 2 + 0) * Hn * G4 + (size_t)(k - En) * G4 + np] = hi;
            g_Up[((size_t)dir * 2 + 1) * Hn * G4 + (size_t)(k - En) * G4 + np] = lo;
        }
    }
    if (idx < 2 * G4) {
        int dir = (int)(idx >> 10), np = (int)(idx & 1023);
        int col = (np & 3) * Hn + (np >> 2);
        g_bp[idx] = (dir ? bb : bf)[col];
    }
    if (idx < 2 * 8 * Tn) {
        ((unsigned*)g_cnt)[idx] = 0u;
    }
    if (idx < Bn) {
        const int* w = word + idx * Tn;
        int c = 0;
        #pragma unroll 8
        for (int t = 0; t < Tn; t++) c += (w[t] != 0);
        g_len[idx] = c;
        out_len[idx] = (float)c;
    }
}

// ---------------- XW GEMM smem layout (55296 B) ----------------
#define R_AHI(buf) ((buf) * 5120)
#define R_ALO(buf) (10240 + (buf) * 5120)
#define R_BHI(buf) (20480 + (buf) * 8704)
#define R_BLO(buf) (37888 + (buf) * 8704)
#define SM_SIZE 55296

__device__ __forceinline__ void gemm_chunk(char* sm, uint32_t smb, int buf,
                                           int wm, int wn, int lane, float acc[8][4])
{
    #pragma unroll
    for (int k16 = 0; k16 < 2; k16++) {
        uint32_t ah[4], al[4];
        {
            int mrow = wm * 16 + ((lane >> 3) & 1) * 8 + (lane & 7);
            int kcol = k16 * 16 + (lane >> 4) * 8;
            uint32_t off = (uint32_t)(mrow * 40 + kcol) * 2;
            ldsm4(ah[0], ah[1], ah[2], ah[3], smb + R_AHI(buf) + off);
            ldsm4(al[0], al[1], al[2], al[3], smb + R_ALO(buf) + off);
        }
        uint32_t bh[16], bl[16];
        {
            int krow = k16 * 16 + ((lane >> 3) & 1) * 8 + (lane & 7);
            #pragma unroll
            for (int nb = 0; nb < 4; nb++) {
                int ncol = wn * 64 + nb * 16 + (lane >> 4) * 8;
                uint32_t off = (uint32_t)(krow * 136 + ncol) * 2;
                ldsm4t(bh[nb * 4 + 0], bh[nb * 4 + 1], bh[nb * 4 + 2], bh[nb * 4 + 3], smb + R_BHI(buf) + off);
                ldsm4t(bl[nb * 4 + 0], bl[nb * 4 + 1], bl[nb * 4 + 2], bl[nb * 4 + 3], smb + R_BLO(buf) + off);
            }
        }
        #pragma unroll
        for (int nf = 0; nf < 8; nf++) {
            mma16816(acc[nf], ah, bh[nf * 2], bh[nf * 2 + 1]);
            mma16816(acc[nf], ah, bl[nf * 2], bl[nf * 2 + 1]);
            mma16816(acc[nf], al, bh[nf * 2], bh[nf * 2 + 1]);
        }
    }
}

// ---------------- XW precompute ----------------
__global__ void __launch_bounds__(256)
xw_kernel(const int* __restrict__ word)
{
    extern __shared__ char sm[];
    const uint32_t smb = smem_u32(sm);

    const int dir = blockIdx.z & 1;
    const int t   = blockIdx.z >> 1;
    const int b0  = blockIdx.x * 64;
    const int ntile = blockIdx.y;
    const int tid = threadIdx.x;
    const int wid = tid >> 5, lane = tid & 31;
    const int wm = wid & 3, wn = wid >> 2;

    float acc[8][4];
    const int colb = ntile * 128 + wn * 64 + (lane & 3) * 2;
    #pragma unroll
    for (int nf = 0; nf < 8; nf++) {
        float2 bb0 = *(const float2*)&g_bp[dir * G4 + colb + nf * 8];
        acc[nf][0] = bb0.x; acc[nf][1] = bb0.y; acc[nf][2] = bb0.x; acc[nf][3] = bb0.y;
    }

    const __nv_bfloat16* whi = g_Wp + ((size_t)dir * 2 + 0) * En * G4 + ntile * 128;
    const __nv_bfloat16* wlo = g_Wp + ((size_t)dir * 2 + 1) * En * G4 + ntile * 128;

    const int am = tid >> 2, akk = (tid & 3) * 8;
    const int bk = tid >> 3, bn0 = (tid & 7) * 16;
    const int tok = word[(size_t)(b0 + am) * Tn + t];
    const __nv_bfloat16* ehi = g_ehi + (size_t)tok * En + akk;
    const __nv_bfloat16* elo = g_elo + (size_t)tok * En + akk;

    uint4 rah, ral, rbh0, rbh1, rbl0, rbl1;
    auto rload = [&](int c) {
        int kb = c * 32;
        rah = *(const uint4*)(ehi + kb);
        ral = *(const uint4*)(elo + kb);
        const __nv_bfloat16* p = whi + (size_t)(kb + bk) * G4 + bn0;
        rbh0 = *(const uint4*)p; rbh1 = *(const uint4*)(p + 8);
        p = wlo + (size_t)(kb + bk) * G4 + bn0;
        rbl0 = *(const uint4*)p; rbl1 = *(const uint4*)(p + 8);
    };
    auto rstore = [&](int buf) {
        *(uint4*)(sm + R_AHI(buf) + (am * 40 + akk) * 2) = rah;
        *(uint4*)(sm + R_ALO(buf) + (am * 40 + akk) * 2) = ral;
        *(uint4*)(sm + R_BHI(buf) + (bk * 136 + bn0) * 2) = rbh0;
        *(uint4*)(sm + R_BHI(buf) + (bk * 136 + bn0) * 2 + 16) = rbh1;
        *(uint4*)(sm + R_BLO(buf) + (bk * 136 + bn0) * 2) = rbl0;
        *(uint4*)(sm + R_BLO(buf) + (bk * 136 + bn0) * 2 + 16) = rbl1;
    };

    rload(0); rstore(0);
    __syncthreads();
    for (int c = 0; c < 4; c++) {
        int buf = c & 1;
        if (c < 3) rload(c + 1);
        gemm_chunk(sm, smb, buf, wm, wn, lane, acc);
        __syncthreads();
        if (c < 3) { rstore(buf ^ 1); __syncthreads(); }
    }

    float* xwp = g_xw + ((size_t)dir * Tn + t) * Bn * G4;
    const int m0 = b0 + wm * 16 + (lane >> 2);
    #pragma unroll
    for (int nf = 0; nf < 8; nf++) {
        *(float2*)&xwp[(size_t)m0 * G4 + colb + nf * 8]       = make_float2(acc[nf][0], acc[nf][1]);
        *(float2*)&xwp[(size_t)(m0 + 8) * G4 + colb + nf * 8] = make_float2(acc[nf][2], acc[nf][3]);
    }
}

// ---------------- persistent recurrent kernel ----------------
// 128 CTAs = (dir 2) x (btile 8) x (ntile 8); one per SM; all 128 steps in one launch.
// SMEM: U resident [256][136] hi+lo; A double-buffered [64][40] hi+lo; Cs epilogue.
#define P_UHI 0
#define P_ULO 69632
#define P_AHI(buf) (139264 + (buf) * 10240)
#define P_ALO(buf) (139264 + (buf) * 10240 + 5120)
#define P_CS 159744
#define P_SIZE 193536

__device__ __forceinline__ void gemm_chunk_p(uint32_t smb, int buf, int kb,
                                             int wm, int wn, int lane, float acc[8][4])
{
    #pragma unroll
    for (int k16 = 0; k16 < 2; k16++) {
        uint32_t ah[4], al[4];
        {
            int mrow = wm * 16 + ((lane >> 3) & 1) * 8 + (lane & 7);
            int kcol = k16 * 16 + (lane >> 4) * 8;
            uint32_t off = (uint32_t)(mrow * 40 + kcol) * 2;
            ldsm4(ah[0], ah[1], ah[2], ah[3], smb + P_AHI(buf) + off);
            ldsm4(al[0], al[1], al[2], al[3], smb + P_ALO(buf) + off);
        }
        uint32_t bh[16], bl[16];
        {
            int krow = kb + k16 * 16 + ((lane >> 3) & 1) * 8 + (lane & 7);
            #pragma unroll
            for (int nb = 0; nb < 4; nb++) {
                int ncol = wn * 64 + nb * 16 + (lane >> 4) * 8;
                uint32_t off = (uint32_t)(krow * 136 + ncol) * 2;
                ldsm4t(bh[nb * 4 + 0], bh[nb * 4 + 1], bh[nb * 4 + 2], bh[nb * 4 + 3], smb + P_UHI + off);
                ldsm4t(bl[nb * 4 + 0], bl[nb * 4 + 1], bl[nb * 4 + 2], bl[nb * 4 + 3], smb + P_ULO + off);
            }
        }
        #pragma unroll
        for (int nf = 0; nf < 8; nf++) {
            mma16816(acc[nf], ah, bh[nf * 2], bh[nf * 2 + 1]);
            mma16816(acc[nf], ah, bl[nf * 2], bl[nf * 2 + 1]);
            mma16816(acc[nf], al, bh[nf * 2], bh[nf * 2 + 1]);
        }
    }
}

__global__ void __launch_bounds__(256)
lstm_persistent()
{
    extern __shared__ char sm[];
    const uint32_t smb = smem_u32(sm);

    const int cta   = blockIdx.x;
    const int dir   = cta & 1;
    const int btile = (cta >> 1) & 7;
    const int ntile = cta >> 4;
    const int b0    = btile * 64;
    const int tid   = threadIdx.x;
    const int wid   = tid >> 5, lane = tid & 31;
    const int wm    = wid & 3, wn = wid >> 2;

    // load resident U (hi+lo) once
    {
        const __nv_bfloat16* uhi = g_Up + ((size_t)dir * 2 + 0) * Hn * G4 + ntile * 128;
        const __nv_bfloat16* ulo = g_Up + ((size_t)dir * 2 + 1) * Hn * G4 + ntile * 128;
        for (int v = tid; v < 256 * 16; v += 256) {
            int row = v >> 4, c8 = (v & 15) * 8;
            *(uint4*)(sm + P_UHI + (row * 136 + c8) * 2) = *(const uint4*)(uhi + (size_t)row * G4 + c8);
            *(uint4*)(sm + P_ULO + (row * 136 + c8) * 2) = *(const uint4*)(ulo + (size_t)row * G4 + c8);
        }
    }
    __syncthreads();

    // static epilogue roles; c-state in registers
    const int erow = tid >> 2;
    const int ecb  = tid & 3;
    float creg[8];
    #pragma unroll
    for (int q = 0; q < 8; q++) creg[q] = 0.0f;

    const int colb = ntile * 128 + wn * 64 + (lane & 3) * 2;
    const int m0   = b0 + wm * 16 + (lane >> 2);
    const int am   = tid >> 2, akk = (tid & 3) * 8;
    unsigned* cnt = &g_cnt[dir][btile][0];

    for (int s = 0; s < Tn; s++) {
        const int t    = dir ? (Tn - 1 - s) : s;
        const int ping = s & 1;

        if (s > 0) {
            if (tid == 0) {
                while (ld_acq(&cnt[s - 1]) < 8u) __nanosleep(64);
            }
            __syncthreads();
        }

        // acc init from precomputed xw (bias folded)
        float acc[8][4];
        const float* xwp = g_xw + ((size_t)dir * Tn + t) * Bn * G4;
        #pragma unroll
        for (int nf = 0; nf < 8; nf++) {
            float2 v0 = *(const float2*)&xwp[(size_t)m0 * G4 + colb + nf * 8];
            float2 v1 = *(const float2*)&xwp[(size_t)(m0 + 8) * G4 + colb + nf * 8];
            acc[nf][0] = v0.x; acc[nf][1] = v0.y; acc[nf][2] = v1.x; acc[nf][3] = v1.y;
        }

        if (s > 0) {
            const __nv_bfloat16* hhi = g_hhi + (size_t)(ping * 2 + dir) * Bn * Hn + (size_t)(b0 + am) * Hn + akk;
            const __nv_bfloat16* hlo = g_hlo + (size_t)(ping * 2 + dir) * Bn * Hn + (size_t)(b0 + am) * Hn + akk;

            uint4 rah = __ldcg((const uint4*)hhi);
            uint4 ral = __ldcg((const uint4*)hlo);
            *(uint4*)(sm + P_AHI(0) + (am * 40 + akk) * 2) = rah;
            *(uint4*)(sm + P_ALO(0) + (am * 40 + akk) * 2) = ral;
            __syncthreads();

            for (int c = 0; c < 8; c++) {
                int buf = c & 1;
                if (c < 7) {
                    rah = __ldcg((const uint4*)(hhi + (c + 1) * 32));
                    ral = __ldcg((const uint4*)(hlo + (c + 1) * 32));
                }
                gemm_chunk_p(smb, buf, c * 32, wm, wn, lane, acc);
                __syncthreads();
                if (c < 7) {
                    *(uint4*)(sm + P_AHI(buf ^ 1) + (am * 40 + akk) * 2) = rah;
                    *(uint4*)(sm + P_ALO(buf ^ 1) + (am * 40 + akk) * 2) = ral;
                    __syncthreads();
                }
            }
        }

        // epilogue via SMEM round-trip
        float* Cs = (float*)(sm + P_CS);
        const int r0 = wm * 16 + (lane >> 2);
        const int cl = wn * 64 + (lane & 3) * 2;
        #pragma unroll
        for (int nf = 0; nf < 8; nf++) {
            *(float2*)&Cs[r0 * 132 + cl + nf * 8]       = make_float2(acc[nf][0], acc[nf][1]);
            *(float2*)&Cs[(r0 + 8) * 132 + cl + nf * 8] = make_float2(acc[nf][2], acc[nf][3]);
        }
        __syncthreads();

        const int b = b0 + erow;
        const int pingW = ping ^ 1;
        __nv_bfloat16* whhi = g_hhi + (size_t)(pingW * 2 + dir) * Bn * Hn + (size_t)b * Hn;
        __nv_bfloat16* whlo = g_hlo + (size_t)(pingW * 2 + dir) * Bn * Hn + (size_t)b * Hn;
        float* hall = g_hall + ((size_t)b * Tn + t) * (2 * Hn) + dir * Hn;

        #pragma unroll
        for (int q = 0; q < 8; q++) {
            const int jl = ecb * 8 + q;
            const int j  = ntile * 32 + jl;
            float iv = Cs[erow * 132 + jl * 4 + 0];
            float fv = Cs[erow * 132 + jl * 4 + 1];
            float gv = Cs[erow * 132 + jl * 4 + 2];
            float ov = Cs[erow * 132 + jl * 4 + 3];
            float ii = sigm(iv);
            float ff = sigm(fv);
            float gg = tanhf(gv);
            float oo = sigm(ov);
            float cn = ff * creg[q] + ii * gg;
            float hn = oo * tanhf(cn);
            creg[q] = cn;
            hall[j] = hn;
            __nv_bfloat16 hi = __float2bfloat16_rn(hn);
            whhi[j] = hi;
            whlo[j] = __float2bfloat16_rn(hn - __bfloat162float(hi));
        }

        __threadfence();
        __syncthreads();
        if (tid == 0) atomicAdd(&cnt[s], 1u);
    }
}

// ---------------- dense + softmax ----------------
__global__ void __launch_bounds__(256)
dense_softmax(const float* __restrict__ Wd, const float* __restrict__ bd, float* __restrict__ probs)
{
    __shared__ float wd_s[KTAGS][2 * Hn];
    __shared__ float bd_s[KTAGS];
    const int tid = threadIdx.x;
    for (int i = tid; i < 2 * Hn * KTAGS; i += 256) {
        int e = i / KTAGS, k = i % KTAGS;
        wd_s[k][e] = Wd[i];
    }
    if (tid < KTAGS) bd_s[tid] = bd[tid];
    __syncthreads();

    const int warp = tid >> 5, lane = tid & 31;
    const size_t row = (size_t)blockIdx.x * 8 + warp;
    const float* h = &g_hall[row * (2 * Hn)];

    float acc[KTAGS];
    #pragma unroll
    for (int k = 0; k < KTAGS; k++) acc[k] = 0.0f;
    #pragma unroll
    for (int q = 0; q < 16; q++) {
        int e = lane + 32 * q;
        float hv = h[e];
        #pragma unroll
        for (int k = 0; k < KTAGS; k++) acc[k] += hv * wd_s[k][e];
    }
    #pragma unroll
    for (int k = 0; k < KTAGS; k++) {
        #pragma unroll
        for (int off = 16; off > 0; off >>= 1)
            acc[k] += __shfl_xor_sync(0xffffffffu, acc[k], off);
        acc[k] += bd_s[k];
    }
    float mx = acc[0];
    #pragma unroll
    for (int k = 1; k < KTAGS; k++) mx = fmaxf(mx, acc[k]);
    float den = 0.0f;
    #pragma unroll
    for (int k = 0; k < KTAGS; k++) den += expf(acc[k] - mx);
    float inv = 1.0f / den;
    #pragma unroll
    for (int k = 0; k < KTAGS; k++) {
        float pv = expf(acc[k] - mx) * inv;
        if (lane == k) probs[row * KTAGS + k] = pv;
    }
}

// ---------------- CRF log-likelihood ----------------
__global__ void crf_kernel(const int* __restrict__ label,
                           const float* __restrict__ trans,
                           const float* __restrict__ probs,
                           float* __restrict__ out_ll)
{
    const int b = blockIdx.x;
    const int lane = threadIdx.x;
    const int len = g_len[b];
    const float* P = probs + (size_t)b * Tn * KTAGS;
    const int* tg = label + (size_t)b * Tn;

    float u = 0.0f;
    for (int t = lane; t < Tn; t += 32)
        if (t < len) u += P[t * KTAGS + tg[t]];
    float bi = 0.0f;
    for (int t = lane; t < Tn - 1; t += 32)
        if (t < len - 1) bi += trans[tg[t] * KTAGS + tg[t + 1]];
    #pragma unroll
    for (int off = 16; off > 0; off >>= 1) {
        u  += __shfl_xor_sync(0xffffffffu, u, off);
        bi += __shfl_xor_sync(0xffffffffu, bi, off);
    }

    const int kk = (lane < KTAGS) ? lane : 0;
    float tr[KTAGS];
    #pragma unroll
    for (int j = 0; j < KTAGS; j++) tr[j] = trans[j * KTAGS + kk];

    float alpha = (lane < KTAGS) ? P[kk] : -1e30f;
    for (int t = 1; t < Tn; t++) {
        float aj[KTAGS];
        #pragma unroll
        for (int j = 0; j < KTAGS; j++) aj[j] = __shfl_sync(0xffffffffu, alpha, j);
        float m = -1e30f;
        #pragma unroll
        for (int j = 0; j < KTAGS; j++) m = fmaxf(m, aj[j] + tr[j]);
        float sum = 0.0f;
        #pragma unroll
        for (int j = 0; j < KTAGS; j++) sum += expf(aj[j] + tr[j] - m);
        float nv = m + logf(sum) + P[t * KTAGS + kk];
        if (t < len && lane < KTAGS) alpha = nv;
    }
    float aj[KTAGS];
    #pragma unroll
    for (int j = 0; j < KTAGS; j++) aj[j] = __shfl_sync(0xffffffffu, alpha, j);
    float m = -1e30f;
    #pragma unroll
    for (int j = 0; j < KTAGS; j++) m = fmaxf(m, aj[j]);
    float sum = 0.0f;
    #pragma unroll
    for (int j = 0; j < KTAGS; j++) sum += expf(aj[j] - m);
    float ln = (len == 0) ? 0.0f : (m + logf(sum));

    if (lane == 0) out_ll[b] = u + bi - ln;
}

// ---------------- launch ----------------
extern "C" void kernel_launch(void* const* d_in, const int* in_sizes, int n_in,
                              void* d_out, int out_size)
{
    const int*   word  = (const int*)d_in[0];
    const int*   label = (const int*)d_in[1];
    const float* emb   = (const float*)d_in[2];
    const float* Wf    = (const float*)d_in[3];
    const float* Uf    = (const float*)d_in[4];
    const float* bf    = (const float*)d_in[5];
    const float* Wb    = (const float*)d_in[6];
    const float* Ub    = (const float*)d_in[7];
    const float* bb    = (const float*)d_in[8];
    const float* Wd    = (const float*)d_in[9];
    const float* bd    = (const float*)d_in[10];
    const float* trans = (const float*)d_in[11];

    float* out      = (float*)d_out;
    float* probs    = out;                                 // 512*128*10
    float* out_len  = out + (size_t)Bn * Tn * KTAGS;       // 512
    float* out_ll   = out_len + Bn;                        // 512

    cudaFuncSetAttribute(xw_kernel, cudaFuncAttributeMaxDynamicSharedMemorySize, SM_SIZE);
    cudaFuncSetAttribute(lstm_persistent, cudaFuncAttributeMaxDynamicSharedMemorySize, P_SIZE);

    const size_t prep_n = (size_t)VOCABN * En;
    prep_kernel<<<(int)((prep_n + 255) / 256), 256>>>(word, emb, Wf, Uf, bf, Wb, Ub, bb, out_len);

    dim3 xwgrid(8, 8, 256);
    xw_kernel<<<xwgrid, 256, SM_SIZE>>>(word);

    lstm_persistent<<<128, 256, P_SIZE>>>();

    dense_softmax<<<8192, 256>>>(Wd, bd, probs);
    crf_kernel<<<Bn, 32>>>(label, trans, probs, out_ll);
}